// round 14
// baseline (speedup 1.0000x reference)
#include <cuda_runtime.h>
#include <cstdint>

#define B_   16
#define CIN  256
#define COUT 256
#define HH   64
#define WW   64
#define MID  64
#define HW   4096
#define WELEM (COUT*CIN*9)

// conv tiling: M=128 (2 rows x 64 cols) x N=128, 256 threads
#define RP       72                  // slab row pitch (floats); interior at col offset 4 (16B aligned)
#define CISTR    296                 // floats per ci; q*296 % 32 == 8q -> conflict-free
#define SLABF    (32*CISTR)          // 9472 floats
#define WPITCH   136                 // B panel row pitch (floats)
#define PANEL_F  (32*WPITCH)         // 4352 floats
#define PANEL_B  (PANEL_F*4)         // 17408 bytes
#define NBUF     4
#define PIPE     3
#define CONV_SMEM (NBUF*PANEL_B + 2*SLABF*4)   // 69632 + 75776 = 145408 (1 CTA/SM)

// ---------------- device scratch ----------------
__device__ float g_pooled[B_*CIN];
__device__ float g_bsoft[B_*16];
__device__ __align__(1024) float g_wfmt[(size_t)B_*2*72*PANEL_F];
__device__ __align__(1024) float g_xtf[(size_t)B_*CIN*HW];      // tf32-rounded x
__device__ float g_bnsum[COUT];
__device__ float g_bnsq[COUT];
__device__ float g_scale[COUT];
__device__ float g_shift[COUT];

// ---------------- helpers ----------------
__device__ __forceinline__ uint32_t smem_u32(const void* p){
    uint32_t a; asm("{ .reg .u64 t; cvta.to.shared.u64 t, %1; cvt.u32.u64 %0, t; }" : "=r"(a) : "l"(p)); return a;
}
__device__ __forceinline__ uint32_t cvt_tf32(float f){
    uint32_t u; asm("cvt.rna.tf32.f32 %0, %1;" : "=r"(u) : "f"(f)); return u;
}
__device__ __forceinline__ uint32_t lds32(uint32_t a){
    uint32_t v; asm("ld.shared.b32 %0, [%1];" : "=r"(v) : "r"(a)); return v;
}
__device__ __forceinline__ void mma_tf32(float* d, const uint32_t* a, uint32_t b0, uint32_t b1){
    asm("mma.sync.aligned.m16n8k8.row.col.f32.tf32.tf32.f32 "
        "{%0,%1,%2,%3}, {%4,%5,%6,%7}, {%8,%9}, {%0,%1,%2,%3};"
        : "+f"(d[0]), "+f"(d[1]), "+f"(d[2]), "+f"(d[3])
        : "r"(a[0]), "r"(a[1]), "r"(a[2]), "r"(a[3]), "r"(b0), "r"(b1));
}
__device__ __forceinline__ void cp16(uint32_t dst, const float* src){
    asm volatile("cp.async.cg.shared.global [%0], [%1], 16;" :: "r"(dst), "l"(src) : "memory");
}
__device__ __forceinline__ void cp_commit(){ asm volatile("cp.async.commit_group;" ::: "memory"); }
__device__ __forceinline__ void cp_wait2(){ asm volatile("cp.async.wait_group 2;" ::: "memory"); }

// ---------------- K1: fused x->tf32 + GAP + BN-accumulator zero ----------------
__global__ void xpool_kernel(const float* __restrict__ x){
    int bc = blockIdx.x;                       // b*CIN + c
    if (bc == 0 && threadIdx.x < 256){         // zero BN accumulators once
        g_bnsum[threadIdx.x] = 0.f;
        g_bnsq[threadIdx.x]  = 0.f;
    }
    const float4* p = (const float4*)(x + (size_t)bc * HW);
    float4* o = (float4*)(g_xtf + (size_t)bc * HW);
    float s = 0.f;
    for (int i = threadIdx.x; i < HW/4; i += 256){
        float4 v = p[i];
        s += v.x + v.y + v.z + v.w;
        float4 w;
        w.x = __uint_as_float(cvt_tf32(v.x));
        w.y = __uint_as_float(cvt_tf32(v.y));
        w.z = __uint_as_float(cvt_tf32(v.z));
        w.w = __uint_as_float(cvt_tf32(v.w));
        o[i] = w;
    }
    __shared__ float red[8];
    for (int of = 16; of; of >>= 1) s += __shfl_down_sync(0xffffffffu, s, of);
    if ((threadIdx.x & 31) == 0) red[threadIdx.x >> 5] = s;
    __syncthreads();
    if (threadIdx.x < 8){
        s = red[threadIdx.x];
        for (int of = 4; of; of >>= 1) s += __shfl_down_sync(0x000000ffu, s, of);
        if (threadIdx.x == 0) g_pooled[bc] = s * (1.f/(float)HW);
    }
}

// ---------------- K2: attention branches ----------------
__global__ void branch_kernel(const float* __restrict__ w1_0, const float* __restrict__ w2_0, const float* __restrict__ b2_0,
                              const float* __restrict__ w1_1, const float* __restrict__ w2_1, const float* __restrict__ b2_1,
                              const float* __restrict__ w1_2, const float* __restrict__ w2_2, const float* __restrict__ b2_2,
                              const float* __restrict__ w1_3, const float* __restrict__ w2_3, const float* __restrict__ b2_3){
    int n = blockIdx.x, b = blockIdx.y;
    const float* w1 = (n==0)?w1_0:(n==1)?w1_1:(n==2)?w1_2:w1_3;
    const float* w2 = (n==0)?w2_0:(n==1)?w2_1:(n==2)?w2_2:w2_3;
    const float* b2 = (n==0)?b2_0:(n==1)?b2_1:(n==2)?b2_2:b2_3;
    __shared__ float pl[CIN]; __shared__ float h[MID]; __shared__ float logit[4];
    int t = threadIdx.x;
    for (int i = t; i < CIN; i += 64) pl[i] = g_pooled[b*CIN + i];
    __syncthreads();
    float acc = 0.f;
    const float* w1r = w1 + t*CIN;
    for (int k = 0; k < CIN; ++k) acc += pl[k] * w1r[k];
    h[t] = fmaxf(acc, 0.f);
    __syncthreads();
    if (t < 4){
        float a = b2[t];
        const float* w2r = w2 + t*MID;
        for (int k = 0; k < MID; ++k) a += h[k] * w2r[k];
        logit[t] = a;
    }
    __syncthreads();
    if (t == 0){
        float m = fmaxf(fmaxf(logit[0],logit[1]), fmaxf(logit[2],logit[3]));
        float e0 = expf(logit[0]-m), e1 = expf(logit[1]-m);
        float e2 = expf(logit[2]-m), e3 = expf(logit[3]-m);
        float inv = 1.f/(e0+e1+e2+e3);
        float* dst = &g_bsoft[(b*4 + n)*4];
        dst[0]=e0*inv; dst[1]=e1*inv; dst[2]=e2*inv; dst[3]=e3*inv;
    }
}

// ---------------- K3: combine (alpha folded in) + format tf32 B panels ----------------
__global__ void combine_kernel(const float* __restrict__ wbank){
    int t = blockIdx.x;
    int ng = t & 3; t >>= 2;
    int cic = t & 7; t >>= 3;
    int oT = t & 1;
    int b  = t >> 1;
    __shared__ float al[4];
    __shared__ float tile[32*289];
    if (threadIdx.x < 4){
        int j = threadIdx.x;
        al[j] = g_bsoft[(b*4+0)*4+j] * g_bsoft[(b*4+1)*4+j]
              * g_bsoft[(b*4+2)*4+j] * g_bsoft[(b*4+3)*4+j];
    }
    __syncthreads();
    float a0 = al[0], a1 = al[1], a2 = al[2], a3 = al[3];

    for (int idx = threadIdx.x; idx < 32*288; idx += 256){
        int n = idx / 288, e = idx - n*288;
        int k = e / 9, tap = e - k*9;
        size_t src = ((size_t)(oT*128 + ng*32 + n)*CIN + cic*32 + k)*9 + tap;
        float v = a0*wbank[src] + a1*wbank[(size_t)WELEM + src]
                + a2*wbank[(size_t)WELEM*2 + src] + a3*wbank[(size_t)WELEM*3 + src];
        tile[n*289 + tap*32 + k] = __uint_as_float(cvt_tf32(v));
    }
    __syncthreads();
    float* dbase = g_wfmt + (size_t)(b*2 + oT)*72*PANEL_F;
    for (int idx = threadIdx.x; idx < 32*288; idx += 256){
        int kt = idx >> 5, n = idx & 31;
        int tap = kt >> 5, k = kt & 31;
        int nperm = ((n & 7) << 2) | (n >> 3);   // lds.128-friendly n order
        dbase[(size_t)(cic*9 + tap)*PANEL_F + k*WPITCH + ng*32 + nperm] = tile[n*289 + kt];
    }
}

// ---------------- K4: tf32 mma.sync implicit-GEMM conv (256 thr, 8 warps) ----------------
// Async double-buffered x slab: chunk c+1 staged via cp.async during chunk c taps.
__global__ void __launch_bounds__(256,1)
conv_kernel(float* __restrict__ out){
    extern __shared__ float sm[];
    float* bpan = sm;                          // NBUF x PANEL_F
    float* slab = sm + NBUF*PANEL_F;           // 2 x SLABF
    const int tid  = threadIdx.x;
    const int lane = tid & 31, wid = tid >> 5;
    const int wm = wid >> 2, wn = wid & 3;     // warp grid 2 x 4
    const int q = lane & 3, g = lane >> 2;
    const int oT = blockIdx.x, b = blockIdx.z;
    const int h0 = blockIdx.y * 2;

    const uint32_t bU    = smem_u32(bpan);
    const uint32_t slabU = smem_u32(slab);
    const float* wbase_g = g_wfmt + (size_t)(b*2 + oT)*72*PANEL_F;
    const float* xtfb = g_xtf + ((size_t)b*CIN << 12);

    float acc[4][4][4];
    #pragma unroll
    for (int i = 0; i < 4; ++i)
        #pragma unroll
        for (int j = 0; j < 4; ++j)
            #pragma unroll
            for (int k = 0; k < 4; ++k) acc[i][j][k] = 0.f;

    // zero BOTH slabs (halo stays zero forever); barrier BEFORE any cp.async
    // so zero-stores cannot race interior cp.async writes.
    for (int i = tid; i < 2*SLABF; i += 256) slab[i] = 0.f;
    __syncthreads();

    // group 0: panel 0 + slab chunk 0 interior
    for (int i = tid; i < PANEL_F/4; i += 256)
        cp16(bU + i*16, wbase_g + (size_t)i*4);
    for (int i = tid; i < 2048; i += 256){
        int ci = i >> 6, rem = i & 63;
        int r = rem >> 4, j = rem & 15;
        int gy = h0 - 1 + r;
        if ((unsigned)gy < 64u)
            cp16(slabU + (uint32_t)((ci*CISTR + r*RP + 4 + j*4)*4),
                 xtfb + ((size_t)ci << 12) + (gy << 6) + j*4);
    }
    cp_commit();
    // groups 1,2: panels 1,2
    #pragma unroll
    for (int p = 1; p < PIPE; ++p){
        for (int i = tid; i < PANEL_F/4; i += 256)
            cp16(bU + (uint32_t)p*PANEL_B + i*16, wbase_g + (size_t)p*PANEL_F + i*4);
        cp_commit();
    }

    for (int c = 0; c < 8; ++c){
        const uint32_t cslabU = slabU + (uint32_t)(c & 1)*(SLABF*4);
        #pragma unroll 1
        for (int t = 0; t < 9; ++t){
            const int p = c*9 + t;
            cp_wait2();                     // panel p (and any older slab group) resident
            __syncthreads();                // visible CTA-wide
            if (p + PIPE < 72){
                const float* src = wbase_g + (size_t)(p+PIPE)*PANEL_F;
                uint32_t dst = bU + (uint32_t)((p+PIPE)&(NBUF-1))*PANEL_B;
                for (int i = tid; i < PANEL_F/4; i += 256)
                    cp16(dst + i*16, src + i*4);
            }
            if (t == 1 && c < 7){
                // stage chunk c+1 slab interior into the other buffer (async)
                const float* xc = xtfb + ((size_t)((c+1)*32) << 12);
                uint32_t sdst = slabU + (uint32_t)(((c+1) & 1)*(SLABF*4));
                for (int i = tid; i < 2048; i += 256){
                    int ci = i >> 6, rem = i & 63;
                    int r = rem >> 4, j = rem & 15;
                    int gy = h0 - 1 + r;
                    if ((unsigned)gy < 64u)
                        cp16(sdst + (uint32_t)((ci*CISTR + r*RP + 4 + j*4)*4),
                             xc + ((size_t)ci << 12) + (gy << 6) + j*4);
                }
            }
            cp_commit();

            // consume tap t from B buffer p&(NBUF-1)
            const int dy = t / 3, dx = t - dy*3;
            const uint32_t aBase = cslabU + (uint32_t)(q*CISTR + (wm + dy)*RP + 3 + g + dx)*4;
            const float4* bp = (const float4*)(bpan + (size_t)(p & (NBUF-1))*PANEL_F
                                               + q*WPITCH + wn*32 + g*4);

            #pragma unroll
            for (int kk = 0; kk < 4; ++kk){
                uint32_t A[4][4];
                const uint32_t a0 = aBase + (uint32_t)kk*(8*CISTR*4);
                #pragma unroll
                for (int mt = 0; mt < 4; ++mt){
                    uint32_t am = a0 + mt*64;
                    A[mt][0] = lds32(am);
                    A[mt][1] = lds32(am + 32);
                    A[mt][2] = lds32(am + 4*CISTR*4);
                    A[mt][3] = lds32(am + 4*CISTR*4 + 32);
                }
                float4 b0v = bp[kk*2*WPITCH];           // +kk*8 k-rows
                float4 b1v = bp[kk*2*WPITCH + WPITCH];  // +4 k-rows
                uint32_t b0a[4] = {__float_as_uint(b0v.x), __float_as_uint(b0v.y),
                                   __float_as_uint(b0v.z), __float_as_uint(b0v.w)};
                uint32_t b1a[4] = {__float_as_uint(b1v.x), __float_as_uint(b1v.y),
                                   __float_as_uint(b1v.z), __float_as_uint(b1v.w)};
                #pragma unroll
                for (int nt = 0; nt < 4; ++nt){
                    #pragma unroll
                    for (int mt = 0; mt < 4; ++mt)
                        mma_tf32(acc[mt][nt], A[mt], b0a[nt], b1a[nt]);
                }
            }
        }
    }

    // epilogue: stores + fused BN partial sums
    const int hh = h0 + wm;
    const int chbase = oT*128 + wn*32;
    float* pb = out + (((size_t)(b*COUT + chbase))*64 + hh)*64;
    #pragma unroll
    for (int nt = 0; nt < 4; ++nt){
        float* pn = pb + (size_t)(nt*8 + 2*q)*HW;
        #pragma unroll
        for (int mt = 0; mt < 4; ++mt){
            int w = mt*16 + g;
            pn[w]          = acc[mt][nt][0];
            pn[HW + w]     = acc[mt][nt][1];
            pn[w + 8]      = acc[mt][nt][2];
            pn[HW + w + 8] = acc[mt][nt][3];
        }
    }
    float s0[4][2], s1[4][2];
    #pragma unroll
    for (int nt = 0; nt < 4; ++nt)
        #pragma unroll
        for (int j = 0; j < 2; ++j){
            float a = 0.f, b2 = 0.f;
            #pragma unroll
            for (int mt = 0; mt < 4; ++mt){
                float u = acc[mt][nt][j], v = acc[mt][nt][j+2];
                a += u + v; b2 += u*u + v*v;
            }
            s0[nt][j] = a; s1[nt][j] = b2;
        }
    #pragma unroll
    for (int off = 16; off >= 4; off >>= 1)
        #pragma unroll
        for (int nt = 0; nt < 4; ++nt)
            #pragma unroll
            for (int j = 0; j < 2; ++j){
                s0[nt][j] += __shfl_down_sync(0xffffffffu, s0[nt][j], off);
                s1[nt][j] += __shfl_down_sync(0xffffffffu, s1[nt][j], off);
            }
    if (lane < 4){
        int chb = chbase + lane*2;
        #pragma unroll
        for (int nt = 0; nt < 4; ++nt)
            #pragma unroll
            for (int j = 0; j < 2; ++j){
                atomicAdd(&g_bnsum[chb + nt*8 + j], s0[nt][j]);
                atomicAdd(&g_bnsq [chb + nt*8 + j], s1[nt][j]);
            }
    }
}

// ---------------- K5: finalize BN stats ----------------
__global__ void finalize_kernel(const float* __restrict__ gamma, const float* __restrict__ beta){
    int c = threadIdx.x;
    const float invN = 1.f/(float)(B_*HW);
    float mean = g_bnsum[c] * invN;
    float var  = g_bnsq[c] * invN - mean*mean;
    float sc = rsqrtf(var + 1e-5f) * gamma[c];
    g_scale[c] = sc;
    g_shift[c] = beta[c] - mean*sc;
}

// ---------------- K6: normalize ----------------
__global__ void norm_kernel(float* __restrict__ out){
    size_t i = (size_t)blockIdx.x*256 + threadIdx.x;
    int c = (int)((i >> 10) & (COUT-1));
    float sc = g_scale[c], sh = g_shift[c];
    float4* p = (float4*)out;
    float4 vv = p[i];
    vv.x = vv.x*sc + sh; vv.y = vv.y*sc + sh;
    vv.z = vv.z*sc + sh; vv.w = vv.w*sc + sh;
    p[i] = vv;
}

// ---------------- launch ----------------
extern "C" void kernel_launch(void* const* d_in, const int* in_sizes, int n_in,
                              void* d_out, int out_size){
    const float* x     = (const float*)d_in[0];
    const float* wbank = (const float*)d_in[1];
    const float* gamma = (const float*)d_in[2];
    const float* beta  = (const float*)d_in[3];
    const float* w1s = (const float*)d_in[4];
    const float* w2s = (const float*)d_in[5];
    const float* b2s = (const float*)d_in[6];
    const float* w1c = (const float*)d_in[7];
    const float* w2c = (const float*)d_in[8];
    const float* b2c = (const float*)d_in[9];
    const float* w1f = (const float*)d_in[10];
    const float* w2f = (const float*)d_in[11];
    const float* b2f = (const float*)d_in[12];
    const float* w1w = (const float*)d_in[13];
    const float* w2w = (const float*)d_in[14];
    const float* b2w = (const float*)d_in[15];
    float* out = (float*)d_out;

    cudaFuncSetAttribute(conv_kernel, cudaFuncAttributeMaxDynamicSharedMemorySize, CONV_SMEM);

    xpool_kernel<<<B_*CIN, 256>>>(x);                                 // 1 (x->tf32 + GAP + BN zero)
    branch_kernel<<<dim3(4, B_), 64>>>(w1s,w2s,b2s, w1c,w2c,b2c,
                                       w1f,w2f,b2f, w1w,w2w,b2w);     // 2
    combine_kernel<<<1024, 256>>>(wbank);                             // 3 (alpha folded in)
    conv_kernel<<<dim3(2, 32, B_), 256, CONV_SMEM>>>(out);            // 4 <- ncu capture window
    finalize_kernel<<<1, 256>>>(gamma, beta);                         // 5
    norm_kernel<<<(int)((size_t)B_*COUT*HW/4/256), 256>>>(out);       // 6
}

// round 15
// speedup vs baseline: 1.1343x; 1.1343x over previous
#include <cuda_runtime.h>
#include <cstdint>

#define B_   16
#define CIN  256
#define COUT 256
#define HH   64
#define WW   64
#define MID  64
#define HW   4096
#define WELEM (COUT*CIN*9)

// conv tiling (R13 525us-validated): M=128 (2 rows x 64 cols) x N=128, 256 threads, 2 CTAs/SM
#define RP       72                  // slab row pitch (floats); interior at col offset 4 (16B aligned)
#define CISTR    296                 // floats per ci; q*296 % 32 == 8q -> conflict-free
#define SLABF    (32*CISTR)          // 9472 floats
#define WPITCH   136                 // B panel row pitch (floats)
#define PANEL_F  (32*WPITCH)         // 4352 floats
#define PANEL_B  (PANEL_F*4)         // 17408 bytes
#define NBUF     4
#define PIPE     3
#define CONV_SMEM (NBUF*PANEL_B + SLABF*4)   // 69632 + 37888 = 107520

// ---------------- device scratch ----------------
__device__ float g_pooled[B_*CIN];
__device__ float g_bsoft[B_*16];
__device__ __align__(1024) float g_wfmt[(size_t)B_*2*72*PANEL_F];
__device__ float g_bnsum[COUT];
__device__ float g_bnsq[COUT];
__device__ float g_scale[COUT];
__device__ float g_shift[COUT];

// ---------------- helpers ----------------
__device__ __forceinline__ uint32_t smem_u32(const void* p){
    uint32_t a; asm("{ .reg .u64 t; cvta.to.shared.u64 t, %1; cvt.u32.u64 %0, t; }" : "=r"(a) : "l"(p)); return a;
}
__device__ __forceinline__ uint32_t cvt_tf32(float f){
    uint32_t u; asm("cvt.rna.tf32.f32 %0, %1;" : "=r"(u) : "f"(f)); return u;
}
__device__ __forceinline__ uint32_t lds32(uint32_t a){
    uint32_t v; asm("ld.shared.b32 %0, [%1];" : "=r"(v) : "r"(a)); return v;
}
__device__ __forceinline__ void mma_tf32(float* d, const uint32_t* a, uint32_t b0, uint32_t b1){
    asm("mma.sync.aligned.m16n8k8.row.col.f32.tf32.tf32.f32 "
        "{%0,%1,%2,%3}, {%4,%5,%6,%7}, {%8,%9}, {%0,%1,%2,%3};"
        : "+f"(d[0]), "+f"(d[1]), "+f"(d[2]), "+f"(d[3])
        : "r"(a[0]), "r"(a[1]), "r"(a[2]), "r"(a[3]), "r"(b0), "r"(b1));
}
__device__ __forceinline__ void cp16(uint32_t dst, const float* src){
    asm volatile("cp.async.cg.shared.global [%0], [%1], 16;" :: "r"(dst), "l"(src) : "memory");
}
__device__ __forceinline__ void cp_commit(){ asm volatile("cp.async.commit_group;" ::: "memory"); }
__device__ __forceinline__ void cp_wait2(){ asm volatile("cp.async.wait_group 2;" ::: "memory"); }

// ---------------- K1: GAP + BN-accumulator zero (read-only) ----------------
__global__ void pool_kernel(const float* __restrict__ x){
    int bc = blockIdx.x;                       // b*CIN + c
    if (bc == 0 && threadIdx.x < 256){         // zero BN accumulators once
        g_bnsum[threadIdx.x] = 0.f;
        g_bnsq[threadIdx.x]  = 0.f;
    }
    const float4* p = (const float4*)(x + (size_t)bc * HW);
    float s = 0.f;
    for (int i = threadIdx.x; i < HW/4; i += 256){
        float4 v = p[i];
        s += v.x + v.y + v.z + v.w;
    }
    __shared__ float red[8];
    for (int of = 16; of; of >>= 1) s += __shfl_down_sync(0xffffffffu, s, of);
    if ((threadIdx.x & 31) == 0) red[threadIdx.x >> 5] = s;
    __syncthreads();
    if (threadIdx.x < 8){
        s = red[threadIdx.x];
        for (int of = 4; of; of >>= 1) s += __shfl_down_sync(0x000000ffu, s, of);
        if (threadIdx.x == 0) g_pooled[bc] = s * (1.f/(float)HW);
    }
}

// ---------------- K2: attention branches ----------------
__global__ void branch_kernel(const float* __restrict__ w1_0, const float* __restrict__ w2_0, const float* __restrict__ b2_0,
                              const float* __restrict__ w1_1, const float* __restrict__ w2_1, const float* __restrict__ b2_1,
                              const float* __restrict__ w1_2, const float* __restrict__ w2_2, const float* __restrict__ b2_2,
                              const float* __restrict__ w1_3, const float* __restrict__ w2_3, const float* __restrict__ b2_3){
    int n = blockIdx.x, b = blockIdx.y;
    const float* w1 = (n==0)?w1_0:(n==1)?w1_1:(n==2)?w1_2:w1_3;
    const float* w2 = (n==0)?w2_0:(n==1)?w2_1:(n==2)?w2_2:w2_3;
    const float* b2 = (n==0)?b2_0:(n==1)?b2_1:(n==2)?b2_2:b2_3;
    __shared__ float pl[CIN]; __shared__ float h[MID]; __shared__ float logit[4];
    int t = threadIdx.x;
    for (int i = t; i < CIN; i += 64) pl[i] = g_pooled[b*CIN + i];
    __syncthreads();
    float acc = 0.f;
    const float* w1r = w1 + t*CIN;
    for (int k = 0; k < CIN; ++k) acc += pl[k] * w1r[k];
    h[t] = fmaxf(acc, 0.f);
    __syncthreads();
    if (t < 4){
        float a = b2[t];
        const float* w2r = w2 + t*MID;
        for (int k = 0; k < MID; ++k) a += h[k] * w2r[k];
        logit[t] = a;
    }
    __syncthreads();
    if (t == 0){
        float m = fmaxf(fmaxf(logit[0],logit[1]), fmaxf(logit[2],logit[3]));
        float e0 = expf(logit[0]-m), e1 = expf(logit[1]-m);
        float e2 = expf(logit[2]-m), e3 = expf(logit[3]-m);
        float inv = 1.f/(e0+e1+e2+e3);
        float* dst = &g_bsoft[(b*4 + n)*4];
        dst[0]=e0*inv; dst[1]=e1*inv; dst[2]=e2*inv; dst[3]=e3*inv;
    }
}

// ---------------- K3: combine (alpha folded, div-free hot loop) ----------------
__global__ void combine_kernel(const float* __restrict__ wbank){
    int t = blockIdx.x;
    int ng = t & 3; t >>= 2;
    int cic = t & 7; t >>= 3;
    int oT = t & 1;
    int b  = t >> 1;
    __shared__ float al[4];
    __shared__ float tile[32*289];
    if (threadIdx.x < 4){
        int j = threadIdx.x;
        al[j] = g_bsoft[(b*4+0)*4+j] * g_bsoft[(b*4+1)*4+j]
              * g_bsoft[(b*4+2)*4+j] * g_bsoft[(b*4+3)*4+j];
    }
    __syncthreads();
    float a0 = al[0], a1 = al[1], a2 = al[2], a3 = al[3];

    // read phase: 36 strided iterations, all indices maintained incrementally.
    // src for (n, e=k*9+tap) is nbase(n) + e (contiguous in e) -> coalesced.
    {
        int n = 0, rem = threadIdx.x;            // rem = e (tid < 288 so n starts 0)
        int k = rem / 9, tap = rem - k*9;        // one-time div
        size_t nbase = ((size_t)(oT*128 + ng*32)*CIN + cic*32)*9;
        const float* w0 = wbank;
        #pragma unroll 4
        for (int it = 0; it < 36; ++it){
            size_t src = nbase + rem;
            float v = a0*w0[src] + a1*w0[(size_t)WELEM + src]
                    + a2*w0[(size_t)WELEM*2 + src] + a3*w0[(size_t)WELEM*3 + src];
            tile[n*289 + tap*32 + k] = __uint_as_float(cvt_tf32(v));
            rem += 256; k += 28; tap += 4;       // 256 = 28*9 + 4
            if (tap >= 9){ tap -= 9; ++k; }
            if (rem >= 288){ rem -= 288; ++n; nbase += (size_t)CIN*9; k -= 32; }
        }
    }
    __syncthreads();
    float* dbase = g_wfmt + (size_t)(b*2 + oT)*72*PANEL_F;
    for (int idx = threadIdx.x; idx < 32*288; idx += 256){
        int kt = idx >> 5, n = idx & 31;
        int tap = kt >> 5, k = kt & 31;
        int nperm = ((n & 7) << 2) | (n >> 3);   // lds.128-friendly n order
        dbase[(size_t)(cic*9 + tap)*PANEL_F + k*WPITCH + ng*32 + nperm] = tile[n*289 + kt];
    }
}

// ---------------- K4: tf32 mma.sync implicit-GEMM conv (R13 body; raw-x input) ----------------
__global__ void __launch_bounds__(256,2)
conv_kernel(const float* __restrict__ x, float* __restrict__ out){
    extern __shared__ float sm[];
    float* bpan = sm;                          // NBUF x PANEL_F
    float* slab = sm + NBUF*PANEL_F;           // SLABF
    const int tid  = threadIdx.x;
    const int lane = tid & 31, wid = tid >> 5;
    const int wm = wid >> 2, wn = wid & 3;     // warp grid 2 x 4
    const int q = lane & 3, g = lane >> 2;
    const int oT = blockIdx.x, b = blockIdx.z;
    const int h0 = blockIdx.y * 2;

    const uint32_t bU    = smem_u32(bpan);
    const uint32_t slabU = smem_u32(slab);
    const float* wbase_g = g_wfmt + (size_t)(b*2 + oT)*72*PANEL_F;
    const float* xtfb = x + ((size_t)b*CIN << 12);

    float acc[4][4][4];
    #pragma unroll
    for (int i = 0; i < 4; ++i)
        #pragma unroll
        for (int j = 0; j < 4; ++j)
            #pragma unroll
            for (int k = 0; k < 4; ++k) acc[i][j][k] = 0.f;

    // zero slab once: halo cols/rows stay zero for the whole kernel
    for (int i = tid; i < SLABF; i += 256) slab[i] = 0.f;

    // prologue: B panels 0..PIPE-1
    #pragma unroll
    for (int p = 0; p < PIPE; ++p){
        for (int i = tid; i < PANEL_F/4; i += 256)
            cp16(bU + (uint32_t)p*PANEL_B + i*16, wbase_g + (size_t)p*PANEL_F + i*4);
        cp_commit();
    }
    __syncthreads();   // zero-fill visible before interior stores

    for (int c = 0; c < 8; ++c){
        #pragma unroll 1
        for (int t = 0; t < 9; ++t){
            const int p = c*9 + t;
            cp_wait2();                     // panel p resident (per-thread)
            __syncthreads();                // visible CTA-wide; prev-tap slab reads drained
            if (p + PIPE < 72){
                const float* src = wbase_g + (size_t)(p+PIPE)*PANEL_F;
                uint32_t dst = bU + (uint32_t)((p+PIPE)&(NBUF-1))*PANEL_B;
                for (int i = tid; i < PANEL_F/4; i += 256)
                    cp16(dst + i*16, src + i*4);
            }
            cp_commit();

            if (t == 0){
                // stage chunk c slab interior: 32 ci x 4 rows x 16 float4 (raw fp32)
                const float* xc = xtfb + ((size_t)(c*32) << 12);
                for (int i = tid; i < 2048; i += 256){
                    int ci = i >> 6, rem = i & 63;
                    int r = rem >> 4, j = rem & 15;
                    int gy = h0 - 1 + r;
                    if ((unsigned)gy < 64u){
                        float4 v = *(const float4*)(xc + ((size_t)ci << 12) + (gy << 6) + j*4);
                        *(float4*)(slab + ci*CISTR + r*RP + 4 + j*4) = v;
                    }
                }
                __syncthreads();
            }

            // consume tap t from B buffer p&(NBUF-1)
            const int dy = t / 3, dx = t - dy*3;
            const uint32_t aBase = slabU + (uint32_t)(q*CISTR + (wm + dy)*RP + 3 + g + dx)*4;
            const float4* bp = (const float4*)(bpan + (size_t)(p & (NBUF-1))*PANEL_F
                                               + q*WPITCH + wn*32 + g*4);

            #pragma unroll
            for (int kk = 0; kk < 4; ++kk){
                uint32_t A[4][4];
                const uint32_t a0 = aBase + (uint32_t)kk*(8*CISTR*4);
                #pragma unroll
                for (int mt = 0; mt < 4; ++mt){
                    uint32_t am = a0 + mt*64;
                    A[mt][0] = lds32(am);
                    A[mt][1] = lds32(am + 32);
                    A[mt][2] = lds32(am + 4*CISTR*4);
                    A[mt][3] = lds32(am + 4*CISTR*4 + 32);
                }
                float4 b0v = bp[kk*2*WPITCH];           // +kk*8 k-rows
                float4 b1v = bp[kk*2*WPITCH + WPITCH];  // +4 k-rows
                uint32_t b0a[4] = {__float_as_uint(b0v.x), __float_as_uint(b0v.y),
                                   __float_as_uint(b0v.z), __float_as_uint(b0v.w)};
                uint32_t b1a[4] = {__float_as_uint(b1v.x), __float_as_uint(b1v.y),
                                   __float_as_uint(b1v.z), __float_as_uint(b1v.w)};
                #pragma unroll
                for (int nt = 0; nt < 4; ++nt){
                    #pragma unroll
                    for (int mt = 0; mt < 4; ++mt)
                        mma_tf32(acc[mt][nt], A[mt], b0a[nt], b1a[nt]);
                }
            }
        }
    }

    // epilogue: stores + fused BN partial sums
    const int hh = h0 + wm;
    const int chbase = oT*128 + wn*32;
    float* pb = out + (((size_t)(b*COUT + chbase))*64 + hh)*64;
    #pragma unroll
    for (int nt = 0; nt < 4; ++nt){
        float* pn = pb + (size_t)(nt*8 + 2*q)*HW;
        #pragma unroll
        for (int mt = 0; mt < 4; ++mt){
            int w = mt*16 + g;
            pn[w]          = acc[mt][nt][0];
            pn[HW + w]     = acc[mt][nt][1];
            pn[w + 8]      = acc[mt][nt][2];
            pn[HW + w + 8] = acc[mt][nt][3];
        }
    }
    float s0[4][2], s1[4][2];
    #pragma unroll
    for (int nt = 0; nt < 4; ++nt)
        #pragma unroll
        for (int j = 0; j < 2; ++j){
            float a = 0.f, b2 = 0.f;
            #pragma unroll
            for (int mt = 0; mt < 4; ++mt){
                float u = acc[mt][nt][j], v = acc[mt][nt][j+2];
                a += u + v; b2 += u*u + v*v;
            }
            s0[nt][j] = a; s1[nt][j] = b2;
        }
    #pragma unroll
    for (int off = 16; off >= 4; off >>= 1)
        #pragma unroll
        for (int nt = 0; nt < 4; ++nt)
            #pragma unroll
            for (int j = 0; j < 2; ++j){
                s0[nt][j] += __shfl_down_sync(0xffffffffu, s0[nt][j], off);
                s1[nt][j] += __shfl_down_sync(0xffffffffu, s1[nt][j], off);
            }
    if (lane < 4){
        int chb = chbase + lane*2;
        #pragma unroll
        for (int nt = 0; nt < 4; ++nt)
            #pragma unroll
            for (int j = 0; j < 2; ++j){
                atomicAdd(&g_bnsum[chb + nt*8 + j], s0[nt][j]);
                atomicAdd(&g_bnsq [chb + nt*8 + j], s1[nt][j]);
            }
    }
}

// ---------------- K5: finalize BN stats ----------------
__global__ void finalize_kernel(const float* __restrict__ gamma, const float* __restrict__ beta){
    int c = threadIdx.x;
    const float invN = 1.f/(float)(B_*HW);
    float mean = g_bnsum[c] * invN;
    float var  = g_bnsq[c] * invN - mean*mean;
    float sc = rsqrtf(var + 1e-5f) * gamma[c];
    g_scale[c] = sc;
    g_shift[c] = beta[c] - mean*sc;
}

// ---------------- K6: normalize ----------------
__global__ void norm_kernel(float* __restrict__ out){
    size_t i = (size_t)blockIdx.x*256 + threadIdx.x;
    int c = (int)((i >> 10) & (COUT-1));
    float sc = g_scale[c], sh = g_shift[c];
    float4* p = (float4*)out;
    float4 vv = p[i];
    vv.x = vv.x*sc + sh; vv.y = vv.y*sc + sh;
    vv.z = vv.z*sc + sh; vv.w = vv.w*sc + sh;
    p[i] = vv;
}

// ---------------- launch ----------------
extern "C" void kernel_launch(void* const* d_in, const int* in_sizes, int n_in,
                              void* d_out, int out_size){
    const float* x     = (const float*)d_in[0];
    const float* wbank = (const float*)d_in[1];
    const float* gamma = (const float*)d_in[2];
    const float* beta  = (const float*)d_in[3];
    const float* w1s = (const float*)d_in[4];
    const float* w2s = (const float*)d_in[5];
    const float* b2s = (const float*)d_in[6];
    const float* w1c = (const float*)d_in[7];
    const float* w2c = (const float*)d_in[8];
    const float* b2c = (const float*)d_in[9];
    const float* w1f = (const float*)d_in[10];
    const float* w2f = (const float*)d_in[11];
    const float* b2f = (const float*)d_in[12];
    const float* w1w = (const float*)d_in[13];
    const float* w2w = (const float*)d_in[14];
    const float* b2w = (const float*)d_in[15];
    float* out = (float*)d_out;

    cudaFuncSetAttribute(conv_kernel, cudaFuncAttributeMaxDynamicSharedMemorySize, CONV_SMEM);

    pool_kernel<<<B_*CIN, 256>>>(x);                                  // 1 (GAP + BN zero)
    branch_kernel<<<dim3(4, B_), 64>>>(w1s,w2s,b2s, w1c,w2c,b2c,
                                       w1f,w2f,b2f, w1w,w2w,b2w);     // 2
    combine_kernel<<<1024, 256>>>(wbank);                             // 3 (alpha folded, div-free)
    conv_kernel<<<dim3(2, 32, B_), 256, CONV_SMEM>>>(x, out);         // 4 <- ncu capture window
    finalize_kernel<<<1, 256>>>(gamma, beta);                         // 5
    norm_kernel<<<(int)((size_t)B_*COUT*HW/4/256), 256>>>(out);       // 6
}

// round 16
// speedup vs baseline: 1.1350x; 1.0006x over previous
#include <cuda_runtime.h>
#include <cstdint>

#define B_   16
#define CIN  256
#define COUT 256
#define HH   64
#define WW   64
#define MID  64
#define HW   4096
#define WELEM (COUT*CIN*9)

// conv tiling (R13 525us-validated): M=128 (2 rows x 64 cols) x N=128, 256 threads, 2 CTAs/SM
#define RP       72                  // slab row pitch (floats); interior at col offset 4 (16B aligned)
#define CISTR    296                 // floats per ci; q*296 % 32 == 8q -> conflict-free
#define SLABF    (32*CISTR)          // 9472 floats
#define WPITCH   136                 // B panel row pitch (floats)
#define PANEL_F  (32*WPITCH)         // 4352 floats
#define PANEL_B  (PANEL_F*4)         // 17408 bytes
#define NBUF     4
#define PIPE     3
#define CONV_SMEM (NBUF*PANEL_B + SLABF*4)   // 69632 + 37888 = 107520

// ---------------- device scratch ----------------
__device__ float g_pooled[B_*CIN];
__device__ float g_bsoft[B_*16];
__device__ __align__(1024) float g_wfmt[(size_t)B_*2*72*PANEL_F];
__device__ float g_bnsum[COUT];
__device__ float g_bnsq[COUT];
__device__ float g_scale[COUT];
__device__ float g_shift[COUT];

// ---------------- helpers ----------------
__device__ __forceinline__ uint32_t smem_u32(const void* p){
    uint32_t a; asm("{ .reg .u64 t; cvta.to.shared.u64 t, %1; cvt.u32.u64 %0, t; }" : "=r"(a) : "l"(p)); return a;
}
__device__ __forceinline__ uint32_t cvt_tf32(float f){
    uint32_t u; asm("cvt.rna.tf32.f32 %0, %1;" : "=r"(u) : "f"(f)); return u;
}
__device__ __forceinline__ uint32_t lds32(uint32_t a){
    uint32_t v; asm("ld.shared.b32 %0, [%1];" : "=r"(v) : "r"(a)); return v;
}
__device__ __forceinline__ void mma_tf32(float* d, const uint32_t* a, uint32_t b0, uint32_t b1){
    asm("mma.sync.aligned.m16n8k8.row.col.f32.tf32.tf32.f32 "
        "{%0,%1,%2,%3}, {%4,%5,%6,%7}, {%8,%9}, {%0,%1,%2,%3};"
        : "+f"(d[0]), "+f"(d[1]), "+f"(d[2]), "+f"(d[3])
        : "r"(a[0]), "r"(a[1]), "r"(a[2]), "r"(a[3]), "r"(b0), "r"(b1));
}
__device__ __forceinline__ void cp16(uint32_t dst, const float* src){
    asm volatile("cp.async.cg.shared.global [%0], [%1], 16;" :: "r"(dst), "l"(src) : "memory");
}
__device__ __forceinline__ void cp_commit(){ asm volatile("cp.async.commit_group;" ::: "memory"); }
__device__ __forceinline__ void cp_wait2(){ asm volatile("cp.async.wait_group 2;" ::: "memory"); }

// ---------------- K1: GAP + BN-accumulator zero (read-only) ----------------
__global__ void pool_kernel(const float* __restrict__ x){
    int bc = blockIdx.x;                       // b*CIN + c
    if (bc == 0 && threadIdx.x < 256){         // zero BN accumulators once
        g_bnsum[threadIdx.x] = 0.f;
        g_bnsq[threadIdx.x]  = 0.f;
    }
    const float4* p = (const float4*)(x + (size_t)bc * HW);
    float s = 0.f;
    for (int i = threadIdx.x; i < HW/4; i += 256){
        float4 v = p[i];
        s += v.x + v.y + v.z + v.w;
    }
    __shared__ float red[8];
    for (int of = 16; of; of >>= 1) s += __shfl_down_sync(0xffffffffu, s, of);
    if ((threadIdx.x & 31) == 0) red[threadIdx.x >> 5] = s;
    __syncthreads();
    if (threadIdx.x < 8){
        s = red[threadIdx.x];
        for (int of = 4; of; of >>= 1) s += __shfl_down_sync(0x000000ffu, s, of);
        if (threadIdx.x == 0) g_pooled[bc] = s * (1.f/(float)HW);
    }
}

// ---------------- K2: attention branches ----------------
__global__ void branch_kernel(const float* __restrict__ w1_0, const float* __restrict__ w2_0, const float* __restrict__ b2_0,
                              const float* __restrict__ w1_1, const float* __restrict__ w2_1, const float* __restrict__ b2_1,
                              const float* __restrict__ w1_2, const float* __restrict__ w2_2, const float* __restrict__ b2_2,
                              const float* __restrict__ w1_3, const float* __restrict__ w2_3, const float* __restrict__ b2_3){
    int n = blockIdx.x, b = blockIdx.y;
    const float* w1 = (n==0)?w1_0:(n==1)?w1_1:(n==2)?w1_2:w1_3;
    const float* w2 = (n==0)?w2_0:(n==1)?w2_1:(n==2)?w2_2:w2_3;
    const float* b2 = (n==0)?b2_0:(n==1)?b2_1:(n==2)?b2_2:b2_3;
    __shared__ float pl[CIN]; __shared__ float h[MID]; __shared__ float logit[4];
    int t = threadIdx.x;
    for (int i = t; i < CIN; i += 64) pl[i] = g_pooled[b*CIN + i];
    __syncthreads();
    float acc = 0.f;
    const float* w1r = w1 + t*CIN;
    for (int k = 0; k < CIN; ++k) acc += pl[k] * w1r[k];
    h[t] = fmaxf(acc, 0.f);
    __syncthreads();
    if (t < 4){
        float a = b2[t];
        const float* w2r = w2 + t*MID;
        for (int k = 0; k < MID; ++k) a += h[k] * w2r[k];
        logit[t] = a;
    }
    __syncthreads();
    if (t == 0){
        float m = fmaxf(fmaxf(logit[0],logit[1]), fmaxf(logit[2],logit[3]));
        float e0 = expf(logit[0]-m), e1 = expf(logit[1]-m);
        float e2 = expf(logit[2]-m), e3 = expf(logit[3]-m);
        float inv = 1.f/(e0+e1+e2+e3);
        float* dst = &g_bsoft[(b*4 + n)*4];
        dst[0]=e0*inv; dst[1]=e1*inv; dst[2]=e2*inv; dst[3]=e3*inv;
    }
}

// ---------------- K3: combine (alpha folded, div-free hot loop) ----------------
__global__ void combine_kernel(const float* __restrict__ wbank){
    int t = blockIdx.x;
    int ng = t & 3; t >>= 2;
    int cic = t & 7; t >>= 3;
    int oT = t & 1;
    int b  = t >> 1;
    __shared__ float al[4];
    __shared__ float tile[32*289];
    if (threadIdx.x < 4){
        int j = threadIdx.x;
        al[j] = g_bsoft[(b*4+0)*4+j] * g_bsoft[(b*4+1)*4+j]
              * g_bsoft[(b*4+2)*4+j] * g_bsoft[(b*4+3)*4+j];
    }
    __syncthreads();
    float a0 = al[0], a1 = al[1], a2 = al[2], a3 = al[3];

    // read phase: 36 strided iterations, all indices maintained incrementally.
    // src for (n, e=k*9+tap) is nbase(n) + e (contiguous in e) -> coalesced.
    {
        int n = 0, rem = threadIdx.x;            // rem = e (tid < 288 so n starts 0)
        int k = rem / 9, tap = rem - k*9;        // one-time div
        size_t nbase = ((size_t)(oT*128 + ng*32)*CIN + cic*32)*9;
        const float* w0 = wbank;
        #pragma unroll 4
        for (int it = 0; it < 36; ++it){
            size_t src = nbase + rem;
            float v = a0*w0[src] + a1*w0[(size_t)WELEM + src]
                    + a2*w0[(size_t)WELEM*2 + src] + a3*w0[(size_t)WELEM*3 + src];
            tile[n*289 + tap*32 + k] = __uint_as_float(cvt_tf32(v));
            rem += 256; k += 28; tap += 4;       // 256 = 28*9 + 4
            if (tap >= 9){ tap -= 9; ++k; }
            if (rem >= 288){ rem -= 288; ++n; nbase += (size_t)CIN*9; k -= 32; }
        }
    }
    __syncthreads();
    float* dbase = g_wfmt + (size_t)(b*2 + oT)*72*PANEL_F;
    for (int idx = threadIdx.x; idx < 32*288; idx += 256){
        int kt = idx >> 5, n = idx & 31;
        int tap = kt >> 5, k = kt & 31;
        int nperm = ((n & 7) << 2) | (n >> 3);   // lds.128-friendly n order
        dbase[(size_t)(cic*9 + tap)*PANEL_F + k*WPITCH + ng*32 + nperm] = tile[n*289 + kt];
    }
}

// ---------------- K4: tf32 mma.sync implicit-GEMM conv (R13 body; raw-x input) ----------------
__global__ void __launch_bounds__(256,2)
conv_kernel(const float* __restrict__ x, float* __restrict__ out){
    extern __shared__ float sm[];
    float* bpan = sm;                          // NBUF x PANEL_F
    float* slab = sm + NBUF*PANEL_F;           // SLABF
    const int tid  = threadIdx.x;
    const int lane = tid & 31, wid = tid >> 5;
    const int wm = wid >> 2, wn = wid & 3;     // warp grid 2 x 4
    const int q = lane & 3, g = lane >> 2;
    const int oT = blockIdx.x, b = blockIdx.z;
    const int h0 = blockIdx.y * 2;

    const uint32_t bU    = smem_u32(bpan);
    const uint32_t slabU = smem_u32(slab);
    const float* wbase_g = g_wfmt + (size_t)(b*2 + oT)*72*PANEL_F;
    const float* xtfb = x + ((size_t)b*CIN << 12);

    float acc[4][4][4];
    #pragma unroll
    for (int i = 0; i < 4; ++i)
        #pragma unroll
        for (int j = 0; j < 4; ++j)
            #pragma unroll
            for (int k = 0; k < 4; ++k) acc[i][j][k] = 0.f;

    // zero slab once: halo cols/rows stay zero for the whole kernel
    for (int i = tid; i < SLABF; i += 256) slab[i] = 0.f;

    // prologue: B panels 0..PIPE-1
    #pragma unroll
    for (int p = 0; p < PIPE; ++p){
        for (int i = tid; i < PANEL_F/4; i += 256)
            cp16(bU + (uint32_t)p*PANEL_B + i*16, wbase_g + (size_t)p*PANEL_F + i*4);
        cp_commit();
    }
    __syncthreads();   // zero-fill visible before interior stores

    for (int c = 0; c < 8; ++c){
        #pragma unroll 1
        for (int t = 0; t < 9; ++t){
            const int p = c*9 + t;
            cp_wait2();                     // panel p resident (per-thread)
            __syncthreads();                // visible CTA-wide; prev-tap slab reads drained
            if (p + PIPE < 72){
                const float* src = wbase_g + (size_t)(p+PIPE)*PANEL_F;
                uint32_t dst = bU + (uint32_t)((p+PIPE)&(NBUF-1))*PANEL_B;
                for (int i = tid; i < PANEL_F/4; i += 256)
                    cp16(dst + i*16, src + i*4);
            }
            cp_commit();

            if (t == 0){
                // stage chunk c slab interior: 32 ci x 4 rows x 16 float4 (raw fp32)
                const float* xc = xtfb + ((size_t)(c*32) << 12);
                for (int i = tid; i < 2048; i += 256){
                    int ci = i >> 6, rem = i & 63;
                    int r = rem >> 4, j = rem & 15;
                    int gy = h0 - 1 + r;
                    if ((unsigned)gy < 64u){
                        float4 v = *(const float4*)(xc + ((size_t)ci << 12) + (gy << 6) + j*4);
                        *(float4*)(slab + ci*CISTR + r*RP + 4 + j*4) = v;
                    }
                }
                __syncthreads();
            }

            // consume tap t from B buffer p&(NBUF-1)
            const int dy = t / 3, dx = t - dy*3;
            const uint32_t aBase = slabU + (uint32_t)(q*CISTR + (wm + dy)*RP + 3 + g + dx)*4;
            const float4* bp = (const float4*)(bpan + (size_t)(p & (NBUF-1))*PANEL_F
                                               + q*WPITCH + wn*32 + g*4);

            #pragma unroll
            for (int kk = 0; kk < 4; ++kk){
                uint32_t A[4][4];
                const uint32_t a0 = aBase + (uint32_t)kk*(8*CISTR*4);
                #pragma unroll
                for (int mt = 0; mt < 4; ++mt){
                    uint32_t am = a0 + mt*64;
                    A[mt][0] = lds32(am);
                    A[mt][1] = lds32(am + 32);
                    A[mt][2] = lds32(am + 4*CISTR*4);
                    A[mt][3] = lds32(am + 4*CISTR*4 + 32);
                }
                float4 b0v = bp[kk*2*WPITCH];           // +kk*8 k-rows
                float4 b1v = bp[kk*2*WPITCH + WPITCH];  // +4 k-rows
                uint32_t b0a[4] = {__float_as_uint(b0v.x), __float_as_uint(b0v.y),
                                   __float_as_uint(b0v.z), __float_as_uint(b0v.w)};
                uint32_t b1a[4] = {__float_as_uint(b1v.x), __float_as_uint(b1v.y),
                                   __float_as_uint(b1v.z), __float_as_uint(b1v.w)};
                #pragma unroll
                for (int nt = 0; nt < 4; ++nt){
                    #pragma unroll
                    for (int mt = 0; mt < 4; ++mt)
                        mma_tf32(acc[mt][nt], A[mt], b0a[nt], b1a[nt]);
                }
            }
        }
    }

    // epilogue: stores + fused BN partial sums
    const int hh = h0 + wm;
    const int chbase = oT*128 + wn*32;
    float* pb = out + (((size_t)(b*COUT + chbase))*64 + hh)*64;
    #pragma unroll
    for (int nt = 0; nt < 4; ++nt){
        float* pn = pb + (size_t)(nt*8 + 2*q)*HW;
        #pragma unroll
        for (int mt = 0; mt < 4; ++mt){
            int w = mt*16 + g;
            pn[w]          = acc[mt][nt][0];
            pn[HW + w]     = acc[mt][nt][1];
            pn[w + 8]      = acc[mt][nt][2];
            pn[HW + w + 8] = acc[mt][nt][3];
        }
    }
    float s0[4][2], s1[4][2];
    #pragma unroll
    for (int nt = 0; nt < 4; ++nt)
        #pragma unroll
        for (int j = 0; j < 2; ++j){
            float a = 0.f, b2 = 0.f;
            #pragma unroll
            for (int mt = 0; mt < 4; ++mt){
                float u = acc[mt][nt][j], v = acc[mt][nt][j+2];
                a += u + v; b2 += u*u + v*v;
            }
            s0[nt][j] = a; s1[nt][j] = b2;
        }
    #pragma unroll
    for (int off = 16; off >= 4; off >>= 1)
        #pragma unroll
        for (int nt = 0; nt < 4; ++nt)
            #pragma unroll
            for (int j = 0; j < 2; ++j){
                s0[nt][j] += __shfl_down_sync(0xffffffffu, s0[nt][j], off);
                s1[nt][j] += __shfl_down_sync(0xffffffffu, s1[nt][j], off);
            }
    if (lane < 4){
        int chb = chbase + lane*2;
        #pragma unroll
        for (int nt = 0; nt < 4; ++nt)
            #pragma unroll
            for (int j = 0; j < 2; ++j){
                atomicAdd(&g_bnsum[chb + nt*8 + j], s0[nt][j]);
                atomicAdd(&g_bnsq [chb + nt*8 + j], s1[nt][j]);
            }
    }
}

// ---------------- K5: finalize BN stats ----------------
__global__ void finalize_kernel(const float* __restrict__ gamma, const float* __restrict__ beta){
    int c = threadIdx.x;
    const float invN = 1.f/(float)(B_*HW);
    float mean = g_bnsum[c] * invN;
    float var  = g_bnsq[c] * invN - mean*mean;
    float sc = rsqrtf(var + 1e-5f) * gamma[c];
    g_scale[c] = sc;
    g_shift[c] = beta[c] - mean*sc;
}

// ---------------- K6: normalize ----------------
__global__ void norm_kernel(float* __restrict__ out){
    size_t i = (size_t)blockIdx.x*256 + threadIdx.x;
    int c = (int)((i >> 10) & (COUT-1));
    float sc = g_scale[c], sh = g_shift[c];
    float4* p = (float4*)out;
    float4 vv = p[i];
    vv.x = vv.x*sc + sh; vv.y = vv.y*sc + sh;
    vv.z = vv.z*sc + sh; vv.w = vv.w*sc + sh;
    p[i] = vv;
}

// ---------------- launch ----------------
extern "C" void kernel_launch(void* const* d_in, const int* in_sizes, int n_in,
                              void* d_out, int out_size){
    const float* x     = (const float*)d_in[0];
    const float* wbank = (const float*)d_in[1];
    const float* gamma = (const float*)d_in[2];
    const float* beta  = (const float*)d_in[3];
    const float* w1s = (const float*)d_in[4];
    const float* w2s = (const float*)d_in[5];
    const float* b2s = (const float*)d_in[6];
    const float* w1c = (const float*)d_in[7];
    const float* w2c = (const float*)d_in[8];
    const float* b2c = (const float*)d_in[9];
    const float* w1f = (const float*)d_in[10];
    const float* w2f = (const float*)d_in[11];
    const float* b2f = (const float*)d_in[12];
    const float* w1w = (const float*)d_in[13];
    const float* w2w = (const float*)d_in[14];
    const float* b2w = (const float*)d_in[15];
    float* out = (float*)d_out;

    cudaFuncSetAttribute(conv_kernel, cudaFuncAttributeMaxDynamicSharedMemorySize, CONV_SMEM);

    pool_kernel<<<B_*CIN, 256>>>(x);                                  // 1 (GAP + BN zero)
    branch_kernel<<<dim3(4, B_), 64>>>(w1s,w2s,b2s, w1c,w2c,b2c,
                                       w1f,w2f,b2f, w1w,w2w,b2w);     // 2
    combine_kernel<<<1024, 256>>>(wbank);                             // 3 (alpha folded, div-free)
    conv_kernel<<<dim3(2, 32, B_), 256, CONV_SMEM>>>(x, out);         // 4 <- ncu capture window
    finalize_kernel<<<1, 256>>>(gamma, beta);                         // 5
    norm_kernel<<<(int)((size_t)B_*COUT*HW/4/256), 256>>>(out);       // 6
}